// round 10
// baseline (speedup 1.0000x reference)
#include <cuda_runtime.h>
#include <cstdint>

// LengthTransform, round 10: TT=32/512-thread blocks (half the blocks, half
// the redundant mask reduction), ballot-based all-ones detect, thread0-only
// param combine + smem broadcast. 16-tap window, cp.async staging.

#define TT       32    // t-values per block (16 warps x 2 t)
#define NTH_B    512
#define W        16    // softmax window taps per t
#define NPAIRS   10    // (W + delta_max)/2
#define SROWS    84    // staged rows per block (span<=63 for r<=2, +20 margin)
#define SVEC     (SROWS * 16)   // 1344 float4

__device__ __forceinline__ void cp_async16(uint32_t saddr, const void* gptr, int src_bytes) {
    asm volatile("cp.async.cg.shared.global [%0], [%1], 16, %2;\n"
                 :: "r"(saddr), "l"(gptr), "r"(src_bytes));
}

__global__ __launch_bounds__(NTH_B, 3)
void lt_fused(const float* __restrict__ x,      // (B,S,64)
              const float* __restrict__ mask,   // (B,S)
              const float* __restrict__ ls_ptr, // scalar
              const int*   __restrict__ tgt_lens,
              float* __restrict__ out_feat,     // (B,T,64)
              float* __restrict__ out_mask,     // (B,T) or null
              int B, int S, int T)
{
    const int b    = blockIdx.y;
    const int t0   = blockIdx.x * TT;
    const int tid  = threadIdx.x;
    const int lane = tid & 31;
    const int wid  = tid >> 5;
    const int tg   = wid * 2;
    const int h    = lane >> 4;          // half-warp id
    const int ln   = lane & 15;

    __shared__ float wpad[TT][32];       // 16 taps, 8-padded both sides
    __shared__ float xs[SROWS * 64];     // staged x rows (21 KB)
    __shared__ float rsum[16];
    __shared__ int   rok[16];
    __shared__ float2 bc;                // {r, allones}

    const int   tl = tgt_lens[b];
    const float ls = ls_ptr[0];

    // ---- per-block mask reduce: sum + ballot all-ones ----
    {
        float part = 0.f;
        bool  ones = true;
        const int S4 = S >> 2;
        const float4* m4 = (const float4*)(mask + (size_t)b * S);
        for (int i = tid; i < S4; i += NTH_B) {
            float4 v = m4[i];
            part += (v.x + v.y) + (v.z + v.w);
            ones = ones && (v.x == 1.f) && (v.y == 1.f) && (v.z == 1.f) && (v.w == 1.f);
        }
        for (int i = (S4 << 2) + tid; i < S; i += NTH_B) {
            float v = mask[(size_t)b * S + i];
            part += v; ones = ones && (v == 1.f);
        }
        #pragma unroll
        for (int o = 16; o > 0; o >>= 1)
            part += __shfl_xor_sync(0xffffffffu, part, o);
        unsigned ob = __all_sync(0xffffffffu, ones);
        if (lane == 0) { rsum[wid] = part; rok[wid] = (int)ob; }
    }
    if (out_mask && tid < TT) {
        int t = t0 + tid;
        if (t < T) out_mask[(size_t)b * T + t] = (t < tl) ? 1.0f : 0.0f;
    }
    __syncthreads();
    if (tid == 0) {
        float sl = 0.f; int ok = 1;
        #pragma unroll
        for (int i = 0; i < 16; i++) { sl += rsum[i]; ok &= rok[i]; }
        bc = make_float2(sl / (float)tl, ok ? 1.0f : 0.0f);
    }
    __syncthreads();

    const float r  = bc.x;
    const bool  allones = (bc.y != 0.0f);
    const float i2 = 1.0f / (2.0f * ls * ls);

    // ---- block-uniform stage window ----
    const int  tF  = min(t0, T - 1);
    const int  tL  = min(t0 + TT - 1, T - 1);
    const int  sbF = min(max(__float2int_rn(r * (float)tF) - 8, 0), S - W);
    const int  sbL = min(max(__float2int_rn(r * (float)tL) - 8, 0), S - W);
    const int  st0 = sbF;
    const bool blockfast = (sbL - sbF >= 0) && (sbL - sbF <= SROWS - 2 * NPAIRS);

    // ---- per-warp window bases ----
    const int   ta  = min(t0 + tg, T - 1);
    const int   tb  = min(t0 + tg + 1, T - 1);
    const float c0  = r * (float)ta;
    const float c1  = r * (float)tb;
    const int   s00 = __float2int_rn(c0);
    const int   s01 = __float2int_rn(c1);
    const int   sb0 = min(max(s00 - 8, 0), S - W);
    const int   sb1 = min(max(s01 - 8, 0), S - W);
    const int   delta = sb1 - sb0;

    // ---- stage via cp.async ----
    if (blockfast) {
        const float4* xg4 = (const float4*)(x + ((size_t)b * S + st0) * 64);
        uint32_t xs_base = (uint32_t)__cvta_generic_to_shared(xs);
        const int avail = (S - st0) * 16;
        #pragma unroll
        for (int k = 0; k < 3; k++) {
            int idx = tid + k * NTH_B;
            if (idx < SVEC) {
                int nb   = (idx < avail) ? 16 : 0;
                int gidx = min(idx, avail - 1);
                cp_async16(xs_base + (uint32_t)idx * 16u, xg4 + gidx, nb);
            }
        }
        asm volatile("cp.async.commit_group;\n" ::: "memory");
    }

    // ---- half-warp softmax: lanes 0-15 -> t_a, 16-31 -> t_b ----
    {
        float4* wz = (float4*)&wpad[tg][0];
        if (lane < 16) wz[lane] = make_float4(0.f, 0.f, 0.f, 0.f);
        __syncwarp();

        const float ch  = h ? c1 : c0;
        const int   s0h = h ? s01 : s00;
        const int   sbh = h ? sb1 : sb0;
        float mv = 1.0f;
        if (!allones) mv = mask[(size_t)b * S + sbh + ln];
        const int   sn = min(max(s0h, 0), S - 1);
        const float dm = (float)sn - ch;
        const float M  = -dm * dm * i2;
        const float d  = (float)(sbh + ln) - ch;
        float lg = allones ? (-d * d * i2)
                           : (mv * (-d * d * i2) - (1.0f - mv) * 1e10f);
        float e  = __expf(lg - M);
        float sm = e;
        #pragma unroll
        for (int o = 8; o > 0; o >>= 1)
            sm += __shfl_xor_sync(0xffffffffu, sm, o);
        wpad[tg + h][8 + ln] = e * __fdividef(1.0f, sm);
    }

    if (blockfast) asm volatile("cp.async.wait_group 0;\n" ::: "memory");
    __syncthreads();

    float4 a0 = {0.f, 0.f, 0.f, 0.f};
    float4 a1 = {0.f, 0.f, 0.f, 0.f};

    if (blockfast && delta >= 0 && delta <= 4) {
        // union sweep from smem: lane covers row 2k+h, D-chunk ln
        const float4* __restrict__ xw4 = ((const float4*)xs) + (sb0 - st0) * 16;
        const float*  __restrict__ w0p = &wpad[tg + 0][8 + h];
        const float*  __restrict__ w1p = &wpad[tg + 1][8 - delta + h];
        #pragma unroll
        for (int k = 0; k < NPAIRS; k++) {
            float4 xv = xw4[k * 32 + lane];
            float  w0 = w0p[2 * k];
            float  w1 = w1p[2 * k];
            a0.x = fmaf(w0, xv.x, a0.x);  a0.y = fmaf(w0, xv.y, a0.y);
            a0.z = fmaf(w0, xv.z, a0.z);  a0.w = fmaf(w0, xv.w, a0.w);
            a1.x = fmaf(w1, xv.x, a1.x);  a1.y = fmaf(w1, xv.y, a1.y);
            a1.z = fmaf(w1, xv.z, a1.z);  a1.w = fmaf(w1, xv.w, a1.w);
        }
    } else {
        // exotic-r / boundary path: per-t independent W-row sweep from global
        const int sbs[2] = {sb0, sb1};
        #pragma unroll
        for (int tt = 0; tt < 2; tt++) {
            const float4* xt4 = (const float4*)(x + ((size_t)b * S + sbs[tt]) * 64);
            const float*  wp  = &wpad[tg + tt][8 + h];
            float4 acc = {0.f, 0.f, 0.f, 0.f};
            #pragma unroll
            for (int pr = 0; pr < W / 2; pr++) {
                float4 xv = xt4[pr * 32 + lane];
                float  w  = wp[pr * 2];
                acc.x = fmaf(w, xv.x, acc.x);  acc.y = fmaf(w, xv.y, acc.y);
                acc.z = fmaf(w, xv.z, acc.z);  acc.w = fmaf(w, xv.w, acc.w);
            }
            if (tt == 0) a0 = acc; else a1 = acc;
        }
    }

    // combine row-halves (butterfly leaves sum in both halves)
    a0.x += __shfl_xor_sync(0xffffffffu, a0.x, 16);
    a0.y += __shfl_xor_sync(0xffffffffu, a0.y, 16);
    a0.z += __shfl_xor_sync(0xffffffffu, a0.z, 16);
    a0.w += __shfl_xor_sync(0xffffffffu, a0.w, 16);
    a1.x += __shfl_xor_sync(0xffffffffu, a1.x, 16);
    a1.y += __shfl_xor_sync(0xffffffffu, a1.y, 16);
    a1.z += __shfl_xor_sync(0xffffffffu, a1.z, 16);
    a1.w += __shfl_xor_sync(0xffffffffu, a1.w, 16);

    // lanes 0-15 store t (tg+0), lanes 16-31 store t (tg+1): one STG.128
    int    tsel = t0 + tg + h;
    float4 av   = h ? a1 : a0;
    if (tsel < T) {
        float4* o4 = (float4*)(out_feat + ((size_t)b * T + tsel) * 64);
        o4[ln] = av;
    }
}

// Generic fallback (any D, any S>=32): one warp per (b,t).
__global__ void length_transform_generic(const float* __restrict__ x,
                                         const float* __restrict__ mask,
                                         const float* __restrict__ ls_ptr,
                                         const int*   __restrict__ tgt_lens,
                                         float* __restrict__ out_feat,
                                         float* __restrict__ out_mask,
                                         int B, int S, int T, int D)
{
    int bt = blockIdx.x;
    int b = bt / T, t = bt % T;
    int lane = threadIdx.x;
    __shared__ float wsh[32];

    float part = 0.f;
    for (int i = lane; i < S; i += 32) part += mask[(size_t)b * S + i];
    #pragma unroll
    for (int o = 16; o > 0; o >>= 1) part += __shfl_xor_sync(0xffffffffu, part, o);
    float sl = part;
    int   tl = tgt_lens[b];
    float r  = sl / (float)tl;
    float ls = ls_ptr[0];
    float i2 = 1.f / (2.f * ls * ls);

    float c  = r * (float)t;
    int   s0 = __float2int_rn(c);
    int   sb = min(max(s0 - 15, 0), max(S - 32, 0));
    int   s  = min(sb + lane, S - 1);
    float d  = (float)s - c;
    float lg0 = -d * d * i2;
    float m  = mask[(size_t)b * S + s];
    float lg = m * lg0 - (1.f - m) * 1e10f;
    if (sb + lane > S - 1) lg = -3.0e38f;
    float mx = lg;
    #pragma unroll
    for (int o = 16; o > 0; o >>= 1) mx = fmaxf(mx, __shfl_xor_sync(0xffffffffu, mx, o));
    float e = __expf(lg - mx);
    float sm = e;
    #pragma unroll
    for (int o = 16; o > 0; o >>= 1) sm += __shfl_xor_sync(0xffffffffu, sm, o);
    wsh[lane] = e / sm;
    __syncwarp();

    for (int dd = lane; dd < D; dd += 32) {
        float acc = 0.f;
        for (int k = 0; k < 32; k++) {
            int ss = sb + k;
            if (ss >= S) break;
            acc = fmaf(wsh[k], x[((size_t)b * S + ss) * D + dd], acc);
        }
        out_feat[((size_t)b * T + t) * D + dd] = acc;
    }
    if (out_mask && lane == 0) out_mask[(size_t)b * T + t] = (t < tl) ? 1.f : 0.f;
}

extern "C" void kernel_launch(void* const* d_in, const int* in_sizes, int n_in,
                              void* d_out, int out_size)
{
    const float* x     = (const float*)d_in[0];
    const float* mask  = (const float*)d_in[1];
    const float* ls    = (const float*)d_in[2];
    const int*   tlens = (const int*)d_in[3];

    const int BSD = in_sizes[0];
    const int BS  = in_sizes[1];
    const int B   = in_sizes[3];
    const int D   = BSD / BS;
    const int S   = BS / B;

    long fp1 = (long)B * (D + 1);
    int  T;
    bool has_mask;
    if (out_size % fp1 == 0) { T = (int)(out_size / fp1); has_mask = true; }
    else                     { T = (int)(out_size / ((long)B * D)); has_mask = false; }

    float* ofeat = (float*)d_out;
    float* omask = has_mask ? ofeat + (size_t)B * T * D : nullptr;

    if (D == 64 && S >= 64) {
        dim3 grid((T + TT - 1) / TT, B);
        lt_fused<<<grid, NTH_B>>>(x, mask, ls, tlens, ofeat, omask, B, S, T);
    } else {
        length_transform_generic<<<B * T, 32>>>(x, mask, ls, tlens, ofeat, omask, B, S, T, D);
    }
}

// round 11
// speedup vs baseline: 1.2555x; 1.2555x over previous
#include <cuda_runtime.h>
#include <cstdint>

// LengthTransform, round 11: round-9 structure (TT=16, 256 thr, 1 prologue
// barrier) + ballot all-ones, float2 packed partials, exact-span cp.async.

#define TT       16    // t-values per block (8 warps x 2 t)
#define NTH_B    256
#define W        16    // softmax window taps per t
#define NPAIRS   10    // (W + delta_max)/2
#define SROWS    56    // staged rows capacity
#define SVEC     (SROWS * 16)   // 896 float4

__device__ __forceinline__ void cp_async16(uint32_t saddr, const void* gptr, int src_bytes) {
    asm volatile("cp.async.cg.shared.global [%0], [%1], 16, %2;\n"
                 :: "r"(saddr), "l"(gptr), "r"(src_bytes));
}

__global__ __launch_bounds__(NTH_B, 6)
void lt_fused(const float* __restrict__ x,      // (B,S,64)
              const float* __restrict__ mask,   // (B,S)
              const float* __restrict__ ls_ptr, // scalar
              const int*   __restrict__ tgt_lens,
              float* __restrict__ out_feat,     // (B,T,64)
              float* __restrict__ out_mask,     // (B,T) or null
              int B, int S, int T)
{
    const int b    = blockIdx.y;
    const int t0   = blockIdx.x * TT;
    const int tid  = threadIdx.x;
    const int lane = tid & 31;
    const int wid  = tid >> 5;
    const int tg   = wid * 2;
    const int h    = lane >> 4;          // half-warp id
    const int ln   = lane & 15;

    __shared__ float  wpad[TT][32];      // 16 taps, 8-padded both sides
    __shared__ float  xs[SROWS * 64];    // staged x rows (14 KB)
    __shared__ float2 rp[8];             // {sum, okflag} per warp

    const int   tl = tgt_lens[b];
    const float ls = ls_ptr[0];

    // ---- per-block mask reduce: sum + ballot all-ones, 1 barrier ----
    {
        float part = 0.f;
        bool  ones = true;
        const int S4 = S >> 2;
        const float4* m4 = (const float4*)(mask + (size_t)b * S);
        for (int i = tid; i < S4; i += NTH_B) {
            float4 v = m4[i];
            part += (v.x + v.y) + (v.z + v.w);
            ones = ones && (v.x == 1.f) && (v.y == 1.f) && (v.z == 1.f) && (v.w == 1.f);
        }
        for (int i = (S4 << 2) + tid; i < S; i += NTH_B) {
            float v = mask[(size_t)b * S + i];
            part += v; ones = ones && (v == 1.f);
        }
        #pragma unroll
        for (int o = 16; o > 0; o >>= 1)
            part += __shfl_xor_sync(0xffffffffu, part, o);
        unsigned ob = __all_sync(0xffffffffu, ones);
        if (lane == 0) rp[wid] = make_float2(part, ob ? 1.0f : 0.0f);
    }
    if (out_mask && tid < TT) {
        int t = t0 + tid;
        if (t < T) out_mask[(size_t)b * T + t] = (t < tl) ? 1.0f : 0.0f;
    }
    __syncthreads();

    float sl = 0.f, okf = 1.0f;
    #pragma unroll
    for (int i = 0; i < 8; i++) {
        float2 v = rp[i];
        sl += v.x;
        okf = fminf(okf, v.y);
    }
    const float r       = sl / (float)tl;
    const bool  allones = (okf != 0.0f);
    const float i2      = 1.0f / (2.0f * ls * ls);

    // ---- block-uniform stage window ----
    const int  tF  = min(t0, T - 1);
    const int  tL  = min(t0 + TT - 1, T - 1);
    const int  sbF = min(max(__float2int_rn(r * (float)tF) - 8, 0), S - W);
    const int  sbL = min(max(__float2int_rn(r * (float)tL) - 8, 0), S - W);
    const int  st0 = sbF;
    const bool blockfast = (sbL - sbF >= 0) && (sbL - sbF <= SROWS - 2 * NPAIRS);

    // ---- per-warp window bases ----
    const int   ta  = min(t0 + tg, T - 1);
    const int   tb  = min(t0 + tg + 1, T - 1);
    const float c0  = r * (float)ta;
    const float c1  = r * (float)tb;
    const int   s00 = __float2int_rn(c0);
    const int   s01 = __float2int_rn(c1);
    const int   sb0 = min(max(s00 - 8, 0), S - W);
    const int   sb1 = min(max(s01 - 8, 0), S - W);
    const int   delta = sb1 - sb0;

    // ---- stage exactly the union span via cp.async ----
    if (blockfast) {
        const float4* xg4 = (const float4*)(x + ((size_t)b * S + st0) * 64);
        uint32_t xs_base = (uint32_t)__cvta_generic_to_shared(xs);
        const int nvec  = (sbL - sbF + W + 4) * 16;   // rows actually needed
        const int avail = (S - st0) * 16;
        #pragma unroll
        for (int k = 0; k < 4; k++) {
            int idx = tid + k * NTH_B;
            if (idx < nvec) {
                int nb   = (idx < avail) ? 16 : 0;
                int gidx = min(idx, avail - 1);
                cp_async16(xs_base + (uint32_t)idx * 16u, xg4 + gidx, nb);
            }
        }
        asm volatile("cp.async.commit_group;\n" ::: "memory");
    }

    // ---- half-warp softmax: lanes 0-15 -> t_a, 16-31 -> t_b ----
    {
        float4* wz = (float4*)&wpad[tg][0];
        if (lane < 16) wz[lane] = make_float4(0.f, 0.f, 0.f, 0.f);
        __syncwarp();

        const float ch  = h ? c1 : c0;
        const int   s0h = h ? s01 : s00;
        const int   sbh = h ? sb1 : sb0;
        float mv = 1.0f;
        if (!allones) mv = mask[(size_t)b * S + sbh + ln];
        const int   sn = min(max(s0h, 0), S - 1);
        const float dm = (float)sn - ch;
        const float M  = -dm * dm * i2;
        const float d  = (float)(sbh + ln) - ch;
        float lg = allones ? (-d * d * i2)
                           : (mv * (-d * d * i2) - (1.0f - mv) * 1e10f);
        float e  = __expf(lg - M);
        float sm = e;
        #pragma unroll
        for (int o = 8; o > 0; o >>= 1)
            sm += __shfl_xor_sync(0xffffffffu, sm, o);
        wpad[tg + h][8 + ln] = e * __fdividef(1.0f, sm);
    }

    if (blockfast) asm volatile("cp.async.wait_group 0;\n" ::: "memory");
    __syncthreads();

    float4 a0 = {0.f, 0.f, 0.f, 0.f};
    float4 a1 = {0.f, 0.f, 0.f, 0.f};

    if (blockfast && delta >= 0 && delta <= 4) {
        // union sweep from smem: lane covers row 2k+h, D-chunk ln
        const float4* __restrict__ xw4 = ((const float4*)xs) + (sb0 - st0) * 16;
        const float*  __restrict__ w0p = &wpad[tg + 0][8 + h];
        const float*  __restrict__ w1p = &wpad[tg + 1][8 - delta + h];
        #pragma unroll
        for (int k = 0; k < NPAIRS; k++) {
            float4 xv = xw4[k * 32 + lane];
            float  w0 = w0p[2 * k];
            float  w1 = w1p[2 * k];
            a0.x = fmaf(w0, xv.x, a0.x);  a0.y = fmaf(w0, xv.y, a0.y);
            a0.z = fmaf(w0, xv.z, a0.z);  a0.w = fmaf(w0, xv.w, a0.w);
            a1.x = fmaf(w1, xv.x, a1.x);  a1.y = fmaf(w1, xv.y, a1.y);
            a1.z = fmaf(w1, xv.z, a1.z);  a1.w = fmaf(w1, xv.w, a1.w);
        }
    } else {
        // exotic-r / boundary path: per-t independent W-row sweep from global
        const int sbs[2] = {sb0, sb1};
        #pragma unroll
        for (int tt = 0; tt < 2; tt++) {
            const float4* xt4 = (const float4*)(x + ((size_t)b * S + sbs[tt]) * 64);
            const float*  wp  = &wpad[tg + tt][8 + h];
            float4 acc = {0.f, 0.f, 0.f, 0.f};
            #pragma unroll
            for (int pr = 0; pr < W / 2; pr++) {
                float4 xv = xt4[pr * 32 + lane];
                float  w  = wp[pr * 2];
                acc.x = fmaf(w, xv.x, acc.x);  acc.y = fmaf(w, xv.y, acc.y);
                acc.z = fmaf(w, xv.z, acc.z);  acc.w = fmaf(w, xv.w, acc.w);
            }
            if (tt == 0) a0 = acc; else a1 = acc;
        }
    }

    // combine row-halves (butterfly leaves sum in both halves)
    a0.x += __shfl_xor_sync(0xffffffffu, a0.x, 16);
    a0.y += __shfl_xor_sync(0xffffffffu, a0.y, 16);
    a0.z += __shfl_xor_sync(0xffffffffu, a0.z, 16);
    a0.w += __shfl_xor_sync(0xffffffffu, a0.w, 16);
    a1.x += __shfl_xor_sync(0xffffffffu, a1.x, 16);
    a1.y += __shfl_xor_sync(0xffffffffu, a1.y, 16);
    a1.z += __shfl_xor_sync(0xffffffffu, a1.z, 16);
    a1.w += __shfl_xor_sync(0xffffffffu, a1.w, 16);

    // lanes 0-15 store t (tg+0), lanes 16-31 store t (tg+1): one STG.128
    int    tsel = t0 + tg + h;
    float4 av   = h ? a1 : a0;
    if (tsel < T) {
        float4* o4 = (float4*)(out_feat + ((size_t)b * T + tsel) * 64);
        o4[ln] = av;
    }
}

// Generic fallback (any D, any S>=32): one warp per (b,t).
__global__ void length_transform_generic(const float* __restrict__ x,
                                         const float* __restrict__ mask,
                                         const float* __restrict__ ls_ptr,
                                         const int*   __restrict__ tgt_lens,
                                         float* __restrict__ out_feat,
                                         float* __restrict__ out_mask,
                                         int B, int S, int T, int D)
{
    int bt = blockIdx.x;
    int b = bt / T, t = bt % T;
    int lane = threadIdx.x;
    __shared__ float wsh[32];

    float part = 0.f;
    for (int i = lane; i < S; i += 32) part += mask[(size_t)b * S + i];
    #pragma unroll
    for (int o = 16; o > 0; o >>= 1) part += __shfl_xor_sync(0xffffffffu, part, o);
    float sl = part;
    int   tl = tgt_lens[b];
    float r  = sl / (float)tl;
    float ls = ls_ptr[0];
    float i2 = 1.f / (2.f * ls * ls);

    float c  = r * (float)t;
    int   s0 = __float2int_rn(c);
    int   sb = min(max(s0 - 15, 0), max(S - 32, 0));
    int   s  = min(sb + lane, S - 1);
    float d  = (float)s - c;
    float lg0 = -d * d * i2;
    float m  = mask[(size_t)b * S + s];
    float lg = m * lg0 - (1.f - m) * 1e10f;
    if (sb + lane > S - 1) lg = -3.0e38f;
    float mx = lg;
    #pragma unroll
    for (int o = 16; o > 0; o >>= 1) mx = fmaxf(mx, __shfl_xor_sync(0xffffffffu, mx, o));
    float e = __expf(lg - mx);
    float sm = e;
    #pragma unroll
    for (int o = 16; o > 0; o >>= 1) sm += __shfl_xor_sync(0xffffffffu, sm, o);
    wsh[lane] = e / sm;
    __syncwarp();

    for (int dd = lane; dd < D; dd += 32) {
        float acc = 0.f;
        for (int k = 0; k < 32; k++) {
            int ss = sb + k;
            if (ss >= S) break;
            acc = fmaf(wsh[k], x[((size_t)b * S + ss) * D + dd], acc);
        }
        out_feat[((size_t)b * T + t) * D + dd] = acc;
    }
    if (out_mask && lane == 0) out_mask[(size_t)b * T + t] = (t < tl) ? 1.f : 0.f;
}

extern "C" void kernel_launch(void* const* d_in, const int* in_sizes, int n_in,
                              void* d_out, int out_size)
{
    const float* x     = (const float*)d_in[0];
    const float* mask  = (const float*)d_in[1];
    const float* ls    = (const float*)d_in[2];
    const int*   tlens = (const int*)d_in[3];

    const int BSD = in_sizes[0];
    const int BS  = in_sizes[1];
    const int B   = in_sizes[3];
    const int D   = BSD / BS;
    const int S   = BS / B;

    long fp1 = (long)B * (D + 1);
    int  T;
    bool has_mask;
    if (out_size % fp1 == 0) { T = (int)(out_size / fp1); has_mask = true; }
    else                     { T = (int)(out_size / ((long)B * D)); has_mask = false; }

    float* ofeat = (float*)d_out;
    float* omask = has_mask ? ofeat + (size_t)B * T * D : nullptr;

    if (D == 64 && S >= 64) {
        dim3 grid((T + TT - 1) / TT, B);
        lt_fused<<<grid, NTH_B>>>(x, mask, ls, tlens, ofeat, omask, B, S, T);
    } else {
        length_transform_generic<<<B * T, 32>>>(x, mask, ls, tlens, ofeat, omask, B, S, T, D);
    }
}

// round 12
// speedup vs baseline: 1.2694x; 1.0111x over previous
#include <cuda_runtime.h>
#include <cstdint>

// LengthTransform, round 12: speculative r = S/tgt_len (verified by ballot
// all-ones), cp.async + softmax issued before the mask reduce completes,
// single block barrier, W=12 window (tail < 2e-8).

#define TT       16    // t-values per block (8 warps x 2 t)
#define NTH_B    256
#define W        12    // softmax window taps per t
#define NPAIRS   8     // (W + delta_max) / 2
#define SROWS    56    // staged rows capacity (span <= 40 gate)
#define WSLOW    16    // slow-path window

__device__ __forceinline__ void cp_async16(uint32_t saddr, const void* gptr, int src_bytes) {
    asm volatile("cp.async.cg.shared.global [%0], [%1], 16, %2;\n"
                 :: "r"(saddr), "l"(gptr), "r"(src_bytes));
}

__global__ __launch_bounds__(NTH_B, 6)
void lt_fused(const float* __restrict__ x,      // (B,S,64)
              const float* __restrict__ mask,   // (B,S)
              const float* __restrict__ ls_ptr, // scalar
              const int*   __restrict__ tgt_lens,
              float* __restrict__ out_feat,     // (B,T,64)
              float* __restrict__ out_mask,     // (B,T) or null
              int B, int S, int T)
{
    const int b    = blockIdx.y;
    const int t0   = blockIdx.x * TT;
    const int tid  = threadIdx.x;
    const int lane = tid & 31;
    const int wid  = tid >> 5;
    const int tg   = wid * 2;
    const int h    = lane >> 4;          // half-warp id
    const int ln   = lane & 15;

    __shared__ float  wpad[TT][32];      // taps at [8..8+W), zero pad around
    __shared__ float  xs[SROWS * 64];    // staged x rows (14 KB)
    __shared__ float2 rp[8];             // {sum, okflag} per warp

    const int   tl = __ldg(tgt_lens + b);
    const float ls = __ldg(ls_ptr);
    const float i2 = 1.0f / (2.0f * ls * ls);

    // ---- SPECULATIVE r (exact when mask is all ones) ----
    const float r = (float)S / (float)tl;

    // ---- block stage window + per-warp bases from speculative r ----
    const int  tF  = min(t0, T - 1);
    const int  tL  = min(t0 + TT - 1, T - 1);
    const int  sbF = min(max(__float2int_rn(r * (float)tF) - 6, 0), S - W);
    const int  sbL = min(max(__float2int_rn(r * (float)tL) - 6, 0), S - W);
    const int  st0 = sbF;
    const bool geom_ok = (sbL - sbF >= 0) && (sbL - sbF <= SROWS - (W + 4));

    const int   ta  = min(t0 + tg, T - 1);
    const int   tb  = min(t0 + tg + 1, T - 1);
    const float c0  = r * (float)ta;
    const float c1  = r * (float)tb;
    const int   s00 = __float2int_rn(c0);
    const int   s01 = __float2int_rn(c1);
    const int   sb0 = min(max(s00 - 6, 0), S - W);
    const int   sb1 = min(max(s01 - 6, 0), S - W);
    const int   delta = sb1 - sb0;
    const bool  warp_ok = (delta >= 0) && (delta <= 4);

    // ---- 1) issue cp.async immediately (depends only on r_spec) ----
    if (geom_ok) {
        const float4* xg4 = (const float4*)(x + ((size_t)b * S + st0) * 64);
        uint32_t xs_base = (uint32_t)__cvta_generic_to_shared(xs);
        const int nvec  = (sbL - sbF + W + 4) * 16;
        const int avail = (S - st0) * 16;
        #pragma unroll
        for (int k = 0; k < 4; k++) {
            int idx = tid + k * NTH_B;
            if (idx < nvec) {
                int nb   = (idx < avail) ? 16 : 0;
                int gidx = min(idx, avail - 1);
                cp_async16(xs_base + (uint32_t)idx * 16u, xg4 + gidx, nb);
            }
        }
        asm volatile("cp.async.commit_group;\n" ::: "memory");
    }

    // ---- 2) issue mask loads (consumed later; latency hidden by softmax) ----
    const int S4 = S >> 2;
    const float4* m4 = (const float4*)(mask + (size_t)b * S);
    float4 vb0, vb1;
    bool   have_fast_mask = (S4 <= 2 * NTH_B) && ((S & 3) == 0);
    if (have_fast_mask) {
        vb0 = (tid           < S4) ? m4[tid]           : make_float4(1.f,1.f,1.f,1.f);
        vb1 = (tid + NTH_B   < S4) ? m4[tid + NTH_B]   : make_float4(1.f,1.f,1.f,1.f);
    }

    if (out_mask && tid < TT) {
        int t = t0 + tid;
        if (t < T) out_mask[(size_t)b * T + t] = (t < tl) ? 1.0f : 0.0f;
    }

    // ---- 3) speculative softmax (pure ALU, no mask): half-warp per t ----
    {
        float4* wz = (float4*)&wpad[tg][0];
        if (lane < 16) wz[lane] = make_float4(0.f, 0.f, 0.f, 0.f);
        __syncwarp();

        const float ch  = h ? c1 : c0;
        const int   s0h = h ? s01 : s00;
        const int   sbh = h ? sb1 : sb0;
        const int   sn = min(max(s0h, 0), S - 1);
        const float dm = (float)sn - ch;
        const float M  = -dm * dm * i2;
        const float d  = (float)(sbh + ln) - ch;
        float e  = (ln < W) ? __expf(-d * d * i2 - M) : 0.f;
        float sm = e;
        #pragma unroll
        for (int o = 8; o > 0; o >>= 1)
            sm += __shfl_xor_sync(0xffffffffu, sm, o);
        wpad[tg + h][8 + ln] = e * __fdividef(1.0f, sm);
    }

    // ---- 4) finish mask reduce (loads already in flight) ----
    {
        float part = 0.f;
        bool  ones = true;
        if (have_fast_mask) {
            if (tid < S4) {
                part += (vb0.x + vb0.y) + (vb0.z + vb0.w);
                ones = ones && (vb0.x==1.f) && (vb0.y==1.f) && (vb0.z==1.f) && (vb0.w==1.f);
            }
            if (tid + NTH_B < S4) {
                part += (vb1.x + vb1.y) + (vb1.z + vb1.w);
                ones = ones && (vb1.x==1.f) && (vb1.y==1.f) && (vb1.z==1.f) && (vb1.w==1.f);
            }
        } else {
            for (int i = tid; i < S4; i += NTH_B) {
                float4 v = m4[i];
                part += (v.x + v.y) + (v.z + v.w);
                ones = ones && (v.x==1.f) && (v.y==1.f) && (v.z==1.f) && (v.w==1.f);
            }
            for (int i = (S4 << 2) + tid; i < S; i += NTH_B) {
                float v = mask[(size_t)b * S + i];
                part += v; ones = ones && (v == 1.f);
            }
        }
        #pragma unroll
        for (int o = 16; o > 0; o >>= 1)
            part += __shfl_xor_sync(0xffffffffu, part, o);
        unsigned ob = __all_sync(0xffffffffu, ones);
        if (lane == 0) rp[wid] = make_float2(part, ob ? 1.0f : 0.0f);
    }

    // ---- 5) wait staged data + ONE barrier ----
    if (geom_ok) asm volatile("cp.async.wait_group 0;\n" ::: "memory");
    __syncthreads();

    float sl = 0.f, okf = 1.0f;
    #pragma unroll
    for (int i = 0; i < 8; i++) {
        float2 v = rp[i];
        sl += v.x;
        okf = fminf(okf, v.y);
    }
    const bool allones = (okf != 0.0f);

    float4 a0 = {0.f, 0.f, 0.f, 0.f};
    float4 a1 = {0.f, 0.f, 0.f, 0.f};

    if (allones && geom_ok && warp_ok) {
        // ---- fast path: speculation verified; sweep union from smem ----
        const float4* __restrict__ xw4 = ((const float4*)xs) + (sb0 - st0) * 16;
        const float*  __restrict__ w0p = &wpad[tg + 0][8 + h];
        const float*  __restrict__ w1p = &wpad[tg + 1][8 - delta + h];
        #pragma unroll
        for (int k = 0; k < NPAIRS; k++) {
            float4 xv = xw4[k * 32 + lane];
            float  w0 = w0p[2 * k];
            float  w1 = w1p[2 * k];
            a0.x = fmaf(w0, xv.x, a0.x);  a0.y = fmaf(w0, xv.y, a0.y);
            a0.z = fmaf(w0, xv.z, a0.z);  a0.w = fmaf(w0, xv.w, a0.w);
            a1.x = fmaf(w1, xv.x, a1.x);  a1.y = fmaf(w1, xv.y, a1.y);
            a1.z = fmaf(w1, xv.z, a1.z);  a1.w = fmaf(w1, xv.w, a1.w);
        }
    } else {
        // ---- slow path: actual r, full mask weights, global sweep ----
        const float ra  = allones ? r : (sl / (float)tl);
        #pragma unroll
        for (int tt = 0; tt < 2; tt++) {
            const int   t  = min(t0 + tg + tt, T - 1);
            const float c  = ra * (float)t;
            const int   s0 = __float2int_rn(c);
            const int   sb = min(max(s0 - 8, 0), max(S - WSLOW, 0));
            // recompute 16-tap masked softmax (half-warp covers taps via 2 rounds)
            if (h == tt) {
                float mv = mask[(size_t)b * S + min(sb + ln, S - 1)];
                const int   sn = min(max(s0, 0), S - 1);
                const float dm = (float)sn - c;
                const float M  = -dm * dm * i2;
                const float d  = (float)(sb + ln) - c;
                float lg = mv * (-d * d * i2) - (1.0f - mv) * 1e10f;
                float e  = __expf(lg - M);
                float sm = e;
                #pragma unroll
                for (int o = 8; o > 0; o >>= 1)
                    sm += __shfl_xor_sync(0xffffffffu, sm, o);
                wpad[tg + tt][8 + ln] = e * __fdividef(1.0f, sm);
            }
            __syncwarp();
            const float4* xt4 = (const float4*)(x + ((size_t)b * S + sb) * 64);
            const float*  wp  = &wpad[tg + tt][8 + h];
            float4 acc = {0.f, 0.f, 0.f, 0.f};
            #pragma unroll
            for (int pr = 0; pr < WSLOW / 2; pr++) {
                float4 xv = xt4[pr * 32 + lane];
                float  w  = wp[pr * 2];
                acc.x = fmaf(w, xv.x, acc.x);  acc.y = fmaf(w, xv.y, acc.y);
                acc.z = fmaf(w, xv.z, acc.z);  acc.w = fmaf(w, xv.w, acc.w);
            }
            if (tt == 0) a0 = acc; else a1 = acc;
        }
    }

    // combine row-halves (butterfly leaves sum in both halves)
    a0.x += __shfl_xor_sync(0xffffffffu, a0.x, 16);
    a0.y += __shfl_xor_sync(0xffffffffu, a0.y, 16);
    a0.z += __shfl_xor_sync(0xffffffffu, a0.z, 16);
    a0.w += __shfl_xor_sync(0xffffffffu, a0.w, 16);
    a1.x += __shfl_xor_sync(0xffffffffu, a1.x, 16);
    a1.y += __shfl_xor_sync(0xffffffffu, a1.y, 16);
    a1.z += __shfl_xor_sync(0xffffffffu, a1.z, 16);
    a1.w += __shfl_xor_sync(0xffffffffu, a1.w, 16);

    int    tsel = t0 + tg + h;
    float4 av   = h ? a1 : a0;
    if (tsel < T) {
        float4* o4 = (float4*)(out_feat + ((size_t)b * T + tsel) * 64);
        o4[ln] = av;
    }
}

// Generic fallback (any D, any S>=32): one warp per (b,t).
__global__ void length_transform_generic(const float* __restrict__ x,
                                         const float* __restrict__ mask,
                                         const float* __restrict__ ls_ptr,
                                         const int*   __restrict__ tgt_lens,
                                         float* __restrict__ out_feat,
                                         float* __restrict__ out_mask,
                                         int B, int S, int T, int D)
{
    int bt = blockIdx.x;
    int b = bt / T, t = bt % T;
    int lane = threadIdx.x;
    __shared__ float wsh[32];

    float part = 0.f;
    for (int i = lane; i < S; i += 32) part += mask[(size_t)b * S + i];
    #pragma unroll
    for (int o = 16; o > 0; o >>= 1) part += __shfl_xor_sync(0xffffffffu, part, o);
    float sl = part;
    int   tl = tgt_lens[b];
    float r  = sl / (float)tl;
    float ls = ls_ptr[0];
    float i2 = 1.f / (2.f * ls * ls);

    float c  = r * (float)t;
    int   s0 = __float2int_rn(c);
    int   sb = min(max(s0 - 15, 0), max(S - 32, 0));
    int   s  = min(sb + lane, S - 1);
    float d  = (float)s - c;
    float lg0 = -d * d * i2;
    float m  = mask[(size_t)b * S + s];
    float lg = m * lg0 - (1.f - m) * 1e10f;
    if (sb + lane > S - 1) lg = -3.0e38f;
    float mx = lg;
    #pragma unroll
    for (int o = 16; o > 0; o >>= 1) mx = fmaxf(mx, __shfl_xor_sync(0xffffffffu, mx, o));
    float e = __expf(lg - mx);
    float sm = e;
    #pragma unroll
    for (int o = 16; o > 0; o >>= 1) sm += __shfl_xor_sync(0xffffffffu, sm, o);
    wsh[lane] = e / sm;
    __syncwarp();

    for (int dd = lane; dd < D; dd += 32) {
        float acc = 0.f;
        for (int k = 0; k < 32; k++) {
            int ss = sb + k;
            if (ss >= S) break;
            acc = fmaf(wsh[k], x[((size_t)b * S + ss) * D + dd], acc);
        }
        out_feat[((size_t)b * T + t) * D + dd] = acc;
    }
    if (out_mask && lane == 0) out_mask[(size_t)b * T + t] = (t < tl) ? 1.f : 0.f;
}

extern "C" void kernel_launch(void* const* d_in, const int* in_sizes, int n_in,
                              void* d_out, int out_size)
{
    const float* x     = (const float*)d_in[0];
    const float* mask  = (const float*)d_in[1];
    const float* ls    = (const float*)d_in[2];
    const int*   tlens = (const int*)d_in[3];

    const int BSD = in_sizes[0];
    const int BS  = in_sizes[1];
    const int B   = in_sizes[3];
    const int D   = BSD / BS;
    const int S   = BS / B;

    long fp1 = (long)B * (D + 1);
    int  T;
    bool has_mask;
    if (out_size % fp1 == 0) { T = (int)(out_size / fp1); has_mask = true; }
    else                     { T = (int)(out_size / ((long)B * D)); has_mask = false; }

    float* ofeat = (float*)d_out;
    float* omask = has_mask ? ofeat + (size_t)B * T * D : nullptr;

    if (D == 64 && S >= 64) {
        dim3 grid((T + TT - 1) / TT, B);
        lt_fused<<<grid, NTH_B>>>(x, mask, ls, tlens, ofeat, omask, B, S, T);
    } else {
        length_transform_generic<<<B * T, 32>>>(x, mask, ls, tlens, ofeat, omask, B, S, T, D);
    }
}